// round 14
// baseline (speedup 1.0000x reference)
#include <cuda_runtime.h>

#define BNUM  32
#define TENC  4096
#define TPRED 1024
#define DHALF 512
#define DFULL 1024
#define NCLS  4
#define ROWS_CTA 256
#define ENC_TS  (TENC / ROWS_CTA)    // 16
#define PRED_TS (TPRED / ROWS_CTA)   // 4
#define NSPLIT  (ENC_TS + PRED_TS)   // 20
#define LN_EPS 1e-5f

__device__ float g_part_e[ENC_TS  * BNUM * NCLS * DHALF];  // 4 MB
__device__ float g_part_p[PRED_TS * BNUM * NCLS * DHALF];  // 1 MB
__device__ float g_mean[BNUM * NCLS * DFULL];              // 512 KB
__device__ unsigned int g_cnt[BNUM * 2 * NCLS];            // [b][half][cls]
__device__ unsigned int g_ticket_b[BNUM];
__device__ unsigned int g_fin_b[BNUM];
__device__ float g_loss_b[BNUM];
__device__ unsigned int g_ticket;

// ---------------------------------------------------------------------------
// Producers: EXACT R13 champion stream shape. grid (NSPLIT, BNUM), 256 thr.
// ---------------------------------------------------------------------------
__global__ void __launch_bounds__(256)
masked_sum_kernel(const float4* __restrict__ enc,
                  const float4* __restrict__ pred,
                  const int*    __restrict__ lab_e,
                  const int*    __restrict__ lab_p) {
    cudaTriggerProgrammaticLaunchCompletion();

    int ts  = blockIdx.x;
    int b   = blockIdx.y;
    int tid = threadIdx.x;
    int col = tid & 127;
    int sub = tid >> 7;                // row parity

    const float4* x;
    const int*    lab;
    float4*       pp;
    int T, tsl, half;
    if (ts < ENC_TS) {
        x = enc;  lab = lab_e; pp = (float4*)g_part_e; T = TENC;  tsl = ts;          half = 0;
    } else {
        x = pred; lab = lab_p; pp = (float4*)g_part_p; T = TPRED; tsl = ts - ENC_TS; half = 1;
    }
    int t0 = tsl * ROWS_CTA;

    __shared__ int slab[ROWS_CTA];
    __shared__ int s_hist[NCLS];
    __shared__ __align__(16) float4 s_acc[NCLS][128];   // 8 KB pair-combine

    if (tid < NCLS) s_hist[tid] = 0;
    int myl = lab[(size_t)b * T + t0 + tid];
    slab[tid] = myl;
    __syncthreads();
    atomicAdd(&s_hist[myl], 1);

    const float4* xp = x + ((size_t)b * T + t0) * (DHALF / 4) + col;

    float4 a0 = {0.f,0.f,0.f,0.f};
    float4 a1 = {0.f,0.f,0.f,0.f};
    float4 a2 = {0.f,0.f,0.f,0.f};
    float4 a3 = {0.f,0.f,0.f,0.f};

    #pragma unroll 8
    for (int t = sub; t < ROWS_CTA; t += 2) {
        float4 v = __ldcs(&xp[(size_t)t * (DHALF / 4)]);
        int c = slab[t];
        a0.x += (c == 0) ? v.x : 0.f;  a0.y += (c == 0) ? v.y : 0.f;
        a0.z += (c == 0) ? v.z : 0.f;  a0.w += (c == 0) ? v.w : 0.f;
        a1.x += (c == 1) ? v.x : 0.f;  a1.y += (c == 1) ? v.y : 0.f;
        a1.z += (c == 1) ? v.z : 0.f;  a1.w += (c == 1) ? v.w : 0.f;
        a2.x += (c == 2) ? v.x : 0.f;  a2.y += (c == 2) ? v.y : 0.f;
        a2.z += (c == 2) ? v.z : 0.f;  a2.w += (c == 2) ? v.w : 0.f;
        a3.x += (c == 3) ? v.x : 0.f;  a3.y += (c == 3) ? v.y : 0.f;
        a3.z += (c == 3) ? v.z : 0.f;  a3.w += (c == 3) ? v.w : 0.f;
    }

    if (sub == 1) {
        s_acc[0][col] = a0; s_acc[1][col] = a1;
        s_acc[2][col] = a2; s_acc[3][col] = a3;
    }
    __syncthreads();
    if (sub == 0) {
        float4 v;
        v = s_acc[0][col]; a0.x += v.x; a0.y += v.y; a0.z += v.z; a0.w += v.w;
        v = s_acc[1][col]; a1.x += v.x; a1.y += v.y; a1.z += v.z; a1.w += v.w;
        v = s_acc[2][col]; a2.x += v.x; a2.y += v.y; a2.z += v.z; a2.w += v.w;
        v = s_acc[3][col]; a3.x += v.x; a3.y += v.y; a3.z += v.z; a3.w += v.w;

        size_t base = (((size_t)tsl * BNUM + b) * NCLS) * (DHALF / 4) + col;
        pp[base + 0 * (DHALF / 4)] = a0;
        pp[base + 1 * (DHALF / 4)] = a1;
        pp[base + 2 * (DHALF / 4)] = a2;
        pp[base + 3 * (DHALF / 4)] = a3;
    }
    if (tid < NCLS)
        atomicAdd(&g_cnt[(b * 2 + half) * NCLS + tid], (unsigned int)s_hist[tid]);

    __threadfence();
    __syncthreads();
    if (tid == 0)
        atomicAdd(&g_ticket_b[b], 1u);
}

// ---------------------------------------------------------------------------
// Tail: grid (8, BNUM), 256 threads. CTA (combo, b), combo = (c, h), reduces
// its slice of the partials into g_mean. 8th CTA per b (ticket) runs LN +
// logits + loss from L2-hot g_mean; global ticket writes the scalar.
// ---------------------------------------------------------------------------
__global__ void __launch_bounds__(256)
tail_kernel(const int*   __restrict__ label,
            const float* __restrict__ norm_w,
            const float* __restrict__ norm_b,
            const float* __restrict__ head_w,
            const float* __restrict__ head_b,
            float*       __restrict__ out) {
    int combo = blockIdx.x;              // 0..7
    int b     = blockIdx.y;
    int c     = combo >> 1;
    int h     = combo & 1;               // 0 = enc, 1 = pred
    int tid   = threadIdx.x;
    int lane  = tid & 31;
    int wid   = tid >> 5;                // 0..7

    // ---- wait for this b's producers ----
    if (tid == 0) {
        volatile unsigned int* t = &g_ticket_b[b];
        while (*t < NSPLIT) __nanosleep(128);
    }
    __syncthreads();
    __threadfence();                     // acquire partials + counts

    // ---- my count (unique reader -> safe reset) ----
    __shared__ float s_invv;
    if (tid == 0) {
        unsigned int cnt = g_cnt[(b * 2 + h) * NCLS + c];
        g_cnt[(b * 2 + h) * NCLS + c] = 0;
        s_invv = 1.f / fmaxf((float)cnt, 1.f);
    }
    __syncthreads();

    // ---- reduce my (b, c, h) slice ----
    {
        int d4 = tid & 127;
        int sh = tid >> 7;               // split parity
        const float4* part = h ? (const float4*)g_part_p : (const float4*)g_part_e;
        int S = h ? PRED_TS : ENC_TS;
        size_t stride = (size_t)BNUM * NCLS * (DHALF / 4);
        size_t base   = ((size_t)b * NCLS + c) * (DHALF / 4) + d4;
        float4 acc = {0.f,0.f,0.f,0.f};
        #pragma unroll
        for (int s = sh; s < S; s += 2) {
            float4 v = part[(size_t)s * stride + base];
            acc.x += v.x; acc.y += v.y; acc.z += v.z; acc.w += v.w;
        }
        __shared__ __align__(16) float4 s_half[128];
        if (sh == 1) s_half[d4] = acc;
        __syncthreads();
        if (sh == 0) {
            float4 v = s_half[d4];
            acc.x += v.x; acc.y += v.y; acc.z += v.z; acc.w += v.w;
            float inv = s_invv;
            acc.x *= inv; acc.y *= inv; acc.z *= inv; acc.w *= inv;
            ((float4*)(g_mean + ((size_t)b * NCLS + c) * DFULL + h * DHALF))[d4] = acc;
        }
    }
    __threadfence();
    __syncthreads();

    // ---- per-b winner: 8th CTA finalizes ----
    __shared__ int s_win;
    if (tid == 0) {
        unsigned int t = atomicAdd(&g_fin_b[b], 1u);
        s_win = (t == 7);
        if (t == 7) { g_fin_b[b] = 0; g_ticket_b[b] = 0; }   // resets for replay
    }
    __syncthreads();
    if (!s_win) return;
    __threadfence();                     // acquire g_mean from peers

    // ---- LN + logits + loss (256 threads, 8 warps) ----
    __shared__ float s_red[2 * NCLS][8];
    __shared__ float s_mu[NCLS], s_rstd[NCLS];
    __shared__ float s_lg[8][NCLS][NCLS];
    __shared__ float s_logits[NCLS][NCLS];

    int gd = tid * 4;
    float4 f[NCLS];
    #pragma unroll
    for (int cc = 0; cc < NCLS; ++cc) {
        f[cc] = *(const float4*)(g_mean + ((size_t)b * NCLS + cc) * DFULL + gd);
        float s = f[cc].x + f[cc].y + f[cc].z + f[cc].w;
        float q = f[cc].x*f[cc].x + f[cc].y*f[cc].y + f[cc].z*f[cc].z + f[cc].w*f[cc].w;
        #pragma unroll
        for (int o = 16; o; o >>= 1) {
            s += __shfl_xor_sync(0xffffffffu, s, o);
            q += __shfl_xor_sync(0xffffffffu, q, o);
        }
        if (lane == 0) { s_red[cc * 2][wid] = s; s_red[cc * 2 + 1][wid] = q; }
    }
    __syncthreads();
    if (tid < NCLS) {
        float s = 0.f, q = 0.f;
        #pragma unroll
        for (int w = 0; w < 8; ++w) { s += s_red[tid * 2][w]; q += s_red[tid * 2 + 1][w]; }
        float mu  = s / (float)DFULL;
        float var = q / (float)DFULL - mu * mu;
        s_mu[tid]   = mu;
        s_rstd[tid] = rsqrtf(var + LN_EPS);
    }
    __syncthreads();

    {
        float4 w4 = *(const float4*)(norm_w + gd);
        float4 b4 = *(const float4*)(norm_b + gd);
        float4 hw[NCLS];
        #pragma unroll
        for (int n = 0; n < NCLS; ++n)
            hw[n] = *(const float4*)(head_w + (size_t)n * DFULL + gd);

        #pragma unroll
        for (int cc = 0; cc < NCLS; ++cc) {
            float mu = s_mu[cc], r = s_rstd[cc];
            float fx = (f[cc].x - mu) * r * w4.x + b4.x;
            float fy = (f[cc].y - mu) * r * w4.y + b4.y;
            float fz = (f[cc].z - mu) * r * w4.z + b4.z;
            float fw = (f[cc].w - mu) * r * w4.w + b4.w;
            #pragma unroll
            for (int n = 0; n < NCLS; ++n) {
                float v = fx * hw[n].x + fy * hw[n].y + fz * hw[n].z + fw * hw[n].w;
                #pragma unroll
                for (int o = 16; o; o >>= 1)
                    v += __shfl_xor_sync(0xffffffffu, v, o);
                if (lane == 0) s_lg[wid][cc][n] = v;
            }
        }
    }
    __syncthreads();
    if (tid < NCLS * NCLS) {
        int cc = tid >> 2, n = tid & 3;
        float v = 0.f;
        #pragma unroll
        for (int w = 0; w < 8; ++w) v += s_lg[w][cc][n];
        s_logits[cc][n] = v + head_b[n];
    }
    __syncthreads();

    if (tid == 0) {
        float sel_sum = 0.f;
        #pragma unroll
        for (int l = 0; l < NCLS; ++l) {
            int lb = label[b * NCLS + l];
            float m = s_logits[lb][0];
            #pragma unroll
            for (int n = 1; n < NCLS; ++n) m = fmaxf(m, s_logits[lb][n]);
            float se = 0.f;
            #pragma unroll
            for (int n = 0; n < NCLS; ++n) se += expf(s_logits[lb][n] - m);
            sel_sum += s_logits[lb][lb] - m - logf(se);
        }
        g_loss_b[b] = sel_sum;
        __threadfence();
        unsigned int t = atomicAdd(&g_ticket, 1u);
        if (t == BNUM - 1) {
            float tot = 0.f;
            #pragma unroll
            for (int i = 0; i < BNUM; ++i) tot += g_loss_b[i];
            out[0] = -tot / (float)(BNUM * NCLS);
            g_ticket = 0;   // reset for next replay
        }
    }
}

// ---------------------------------------------------------------------------
extern "C" void kernel_launch(void* const* d_in, const int* in_sizes, int n_in,
                              void* d_out, int out_size) {
    const float* enc_out = (const float*)d_in[0];
    const float* pred_out = (const float*)d_in[1];
    const int*   frame_label  = (const int*)d_in[2];
    const int*   frame_tlabel = (const int*)d_in[3];
    const int*   label  = (const int*)d_in[4];
    const float* norm_w = (const float*)d_in[5];
    const float* norm_b = (const float*)d_in[6];
    const float* head_w = (const float*)d_in[7];
    const float* head_b = (const float*)d_in[8];
    float* out = (float*)d_out;

    masked_sum_kernel<<<dim3(NSPLIT, BNUM), 256>>>(
        (const float4*)enc_out, (const float4*)pred_out,
        frame_label, frame_tlabel);

    {
        cudaLaunchConfig_t cfg = {};
        cfg.gridDim  = dim3(8, BNUM);
        cfg.blockDim = dim3(256);
        cfg.dynamicSmemBytes = 0;
        cfg.stream = 0;
        cudaLaunchAttribute attr[1];
        attr[0].id = cudaLaunchAttributeProgrammaticStreamSerialization;
        attr[0].val.programmaticStreamSerializationAllowed = 1;
        cfg.attrs = attr;
        cfg.numAttrs = 1;
        cudaLaunchKernelEx(&cfg, tail_kernel, label, norm_w, norm_b,
                           head_w, head_b, (float*)out);
    }
}

// round 15
// speedup vs baseline: 1.2591x; 1.2591x over previous
#include <cuda_runtime.h>

#define BNUM  32
#define TENC  4096
#define TPRED 1024
#define DHALF 512
#define DFULL 1024
#define NCLS  4
#define ROWS_CTA 256
#define ENC_TS  (TENC / ROWS_CTA)    // 16
#define PRED_TS (TPRED / ROWS_CTA)   // 4
#define NSPLIT  (ENC_TS + PRED_TS)   // 20
#define LN_EPS 1e-5f

__device__ float g_part_e[ENC_TS  * BNUM * NCLS * DHALF];  // 4 MB
__device__ float g_part_p[PRED_TS * BNUM * NCLS * DHALF];  // 1 MB
__device__ unsigned int g_cnt[BNUM * 2 * NCLS];            // [b][half][cls]
__device__ float g_loss_b[BNUM];
__device__ unsigned int g_ticket;

// ---------------------------------------------------------------------------
// Producers: champion stream shape (R11/R13). grid (NSPLIT, BNUM), 256 thr,
// parity pair-combine, inline count publish.
// ---------------------------------------------------------------------------
__global__ void __launch_bounds__(256)
masked_sum_kernel(const float4* __restrict__ enc,
                  const float4* __restrict__ pred,
                  const int*    __restrict__ lab_e,
                  const int*    __restrict__ lab_p) {
    int ts  = blockIdx.x;
    int b   = blockIdx.y;
    int tid = threadIdx.x;
    int col = tid & 127;
    int sub = tid >> 7;                // row parity

    const float4* x;
    const int*    lab;
    float4*       pp;
    int T, tsl, half;
    if (ts < ENC_TS) {
        x = enc;  lab = lab_e; pp = (float4*)g_part_e; T = TENC;  tsl = ts;          half = 0;
    } else {
        x = pred; lab = lab_p; pp = (float4*)g_part_p; T = TPRED; tsl = ts - ENC_TS; half = 1;
    }
    int t0 = tsl * ROWS_CTA;

    __shared__ int slab[ROWS_CTA];
    __shared__ int s_hist[NCLS];
    __shared__ __align__(16) float4 s_acc[NCLS][128];   // 8 KB pair-combine

    if (tid < NCLS) s_hist[tid] = 0;
    int myl = lab[(size_t)b * T + t0 + tid];
    slab[tid] = myl;
    __syncthreads();
    atomicAdd(&s_hist[myl], 1);

    const float4* xp = x + ((size_t)b * T + t0) * (DHALF / 4) + col;

    float4 a0 = {0.f,0.f,0.f,0.f};
    float4 a1 = {0.f,0.f,0.f,0.f};
    float4 a2 = {0.f,0.f,0.f,0.f};
    float4 a3 = {0.f,0.f,0.f,0.f};

    #pragma unroll 8
    for (int t = sub; t < ROWS_CTA; t += 2) {
        float4 v = __ldcs(&xp[(size_t)t * (DHALF / 4)]);
        int c = slab[t];
        a0.x += (c == 0) ? v.x : 0.f;  a0.y += (c == 0) ? v.y : 0.f;
        a0.z += (c == 0) ? v.z : 0.f;  a0.w += (c == 0) ? v.w : 0.f;
        a1.x += (c == 1) ? v.x : 0.f;  a1.y += (c == 1) ? v.y : 0.f;
        a1.z += (c == 1) ? v.z : 0.f;  a1.w += (c == 1) ? v.w : 0.f;
        a2.x += (c == 2) ? v.x : 0.f;  a2.y += (c == 2) ? v.y : 0.f;
        a2.z += (c == 2) ? v.z : 0.f;  a2.w += (c == 2) ? v.w : 0.f;
        a3.x += (c == 3) ? v.x : 0.f;  a3.y += (c == 3) ? v.y : 0.f;
        a3.z += (c == 3) ? v.z : 0.f;  a3.w += (c == 3) ? v.w : 0.f;
    }

    if (sub == 1) {
        s_acc[0][col] = a0; s_acc[1][col] = a1;
        s_acc[2][col] = a2; s_acc[3][col] = a3;
    }
    __syncthreads();
    if (sub == 0) {
        float4 v;
        v = s_acc[0][col]; a0.x += v.x; a0.y += v.y; a0.z += v.z; a0.w += v.w;
        v = s_acc[1][col]; a1.x += v.x; a1.y += v.y; a1.z += v.z; a1.w += v.w;
        v = s_acc[2][col]; a2.x += v.x; a2.y += v.y; a2.z += v.z; a2.w += v.w;
        v = s_acc[3][col]; a3.x += v.x; a3.y += v.y; a3.z += v.z; a3.w += v.w;

        size_t base = (((size_t)tsl * BNUM + b) * NCLS) * (DHALF / 4) + col;
        pp[base + 0 * (DHALF / 4)] = a0;
        pp[base + 1 * (DHALF / 4)] = a1;
        pp[base + 2 * (DHALF / 4)] = a2;
        pp[base + 3 * (DHALF / 4)] = a3;
    }
    if (tid < NCLS)
        atomicAdd(&g_cnt[(b * 2 + half) * NCLS + tid], (unsigned int)s_hist[tid]);
}

// ---------------------------------------------------------------------------
// Tail: grid BNUM, 1024 threads. Parallel (class, half, d4) mapping — every
// partial load issues concurrently (max MLP). Counts from g_cnt (reset
// after read). LN + logits + loss on threads 0..255; global ticket scalar.
// ---------------------------------------------------------------------------
__global__ void __launch_bounds__(1024)
tail_kernel(const int*   __restrict__ label,
            const float* __restrict__ norm_w,
            const float* __restrict__ norm_b,
            const float* __restrict__ head_w,
            const float* __restrict__ head_b,
            float*       __restrict__ out) {
    int b    = blockIdx.x;
    int tid  = threadIdx.x;
    int lane = tid & 31;
    int wid  = tid >> 5;                 // 0..31

    __shared__ __align__(16) float s_feat[NCLS][DFULL];   // 16 KB
    __shared__ float s_inv[2][NCLS];

    // ---- counts from producer-published histograms ----
    if (tid < 2 * NCLS) {
        s_inv[tid >> 2][tid & 3] =
            1.f / fmaxf((float)g_cnt[b * 2 * NCLS + tid], 1.f);
        g_cnt[b * 2 * NCLS + tid] = 0;   // reset for next replay
    }
    __syncthreads();

    // ---- fully parallel split-reduce: c = tid>>8, h = (tid>>7)&1 ----
    {
        int c  = tid >> 8;
        int h  = (tid >> 7) & 1;
        int d4 = tid & 127;
        const float4* part;
        int S;
        if (h == 0) { part = (const float4*)g_part_e; S = ENC_TS; }
        else        { part = (const float4*)g_part_p; S = PRED_TS; }
        size_t stride = (size_t)BNUM * NCLS * (DHALF / 4);
        size_t base   = ((size_t)b * NCLS + c) * (DHALF / 4) + d4;
        float4 acc = {0.f,0.f,0.f,0.f};
        #pragma unroll 16
        for (int s = 0; s < S; ++s) {
            float4 v = part[(size_t)s * stride + base];
            acc.x += v.x; acc.y += v.y; acc.z += v.z; acc.w += v.w;
        }
        float inv = s_inv[h][c];
        acc.x *= inv; acc.y *= inv; acc.z *= inv; acc.w *= inv;
        *(float4*)&s_feat[c][h * DHALF + d4 * 4] = acc;
    }
    __syncthreads();

    // ---- LN stats + logits on threads 0..255 (8 warps) ----
    __shared__ float s_red[2 * NCLS][8];
    __shared__ float s_mu[NCLS], s_rstd[NCLS];
    __shared__ float s_lg[8][NCLS][NCLS];
    __shared__ float s_logits[NCLS][NCLS];

    int gd = (tid & 255) * 4;
    float4 f[NCLS];
    if (tid < 256) {
        #pragma unroll
        for (int c = 0; c < NCLS; ++c) {
            f[c] = *(const float4*)&s_feat[c][gd];
            float s = f[c].x + f[c].y + f[c].z + f[c].w;
            float q = f[c].x*f[c].x + f[c].y*f[c].y + f[c].z*f[c].z + f[c].w*f[c].w;
            #pragma unroll
            for (int o = 16; o; o >>= 1) {
                s += __shfl_xor_sync(0xffffffffu, s, o);
                q += __shfl_xor_sync(0xffffffffu, q, o);
            }
            if (lane == 0) { s_red[c * 2][wid] = s; s_red[c * 2 + 1][wid] = q; }
        }
    }
    __syncthreads();
    if (tid < NCLS) {
        float s = 0.f, q = 0.f;
        #pragma unroll
        for (int w = 0; w < 8; ++w) { s += s_red[tid * 2][w]; q += s_red[tid * 2 + 1][w]; }
        float mu  = s / (float)DFULL;
        float var = q / (float)DFULL - mu * mu;
        s_mu[tid]   = mu;
        s_rstd[tid] = rsqrtf(var + LN_EPS);
    }
    __syncthreads();

    if (tid < 256) {
        float4 w4 = *(const float4*)(norm_w + gd);
        float4 b4 = *(const float4*)(norm_b + gd);
        float4 hw[NCLS];
        #pragma unroll
        for (int n = 0; n < NCLS; ++n)
            hw[n] = *(const float4*)(head_w + (size_t)n * DFULL + gd);

        #pragma unroll
        for (int c = 0; c < NCLS; ++c) {
            float mu = s_mu[c], r = s_rstd[c];
            float fx = (f[c].x - mu) * r * w4.x + b4.x;
            float fy = (f[c].y - mu) * r * w4.y + b4.y;
            float fz = (f[c].z - mu) * r * w4.z + b4.z;
            float fw = (f[c].w - mu) * r * w4.w + b4.w;
            #pragma unroll
            for (int n = 0; n < NCLS; ++n) {
                float v = fx * hw[n].x + fy * hw[n].y + fz * hw[n].z + fw * hw[n].w;
                #pragma unroll
                for (int o = 16; o; o >>= 1)
                    v += __shfl_xor_sync(0xffffffffu, v, o);
                if (lane == 0) s_lg[wid][c][n] = v;
            }
        }
    }
    __syncthreads();
    if (tid < NCLS * NCLS) {
        int c = tid >> 2, n = tid & 3;
        float v = 0.f;
        #pragma unroll
        for (int w = 0; w < 8; ++w) v += s_lg[w][c][n];
        s_logits[c][n] = v + head_b[n];
    }
    __syncthreads();

    // ---- per-b loss + global scalar ----
    if (tid == 0) {
        float sel_sum = 0.f;
        #pragma unroll
        for (int l = 0; l < NCLS; ++l) {
            int lb = label[b * NCLS + l];
            float m = s_logits[lb][0];
            #pragma unroll
            for (int n = 1; n < NCLS; ++n) m = fmaxf(m, s_logits[lb][n]);
            float se = 0.f;
            #pragma unroll
            for (int n = 0; n < NCLS; ++n) se += expf(s_logits[lb][n] - m);
            sel_sum += s_logits[lb][lb] - m - logf(se);
        }
        g_loss_b[b] = sel_sum;
        __threadfence();
        unsigned int t = atomicAdd(&g_ticket, 1u);
        if (t == BNUM - 1) {
            float tot = 0.f;
            #pragma unroll
            for (int i = 0; i < BNUM; ++i) tot += g_loss_b[i];
            out[0] = -tot / (float)(BNUM * NCLS);
            g_ticket = 0;   // reset for next replay
        }
    }
}

// ---------------------------------------------------------------------------
extern "C" void kernel_launch(void* const* d_in, const int* in_sizes, int n_in,
                              void* d_out, int out_size) {
    const float* enc_out = (const float*)d_in[0];
    const float* pred_out = (const float*)d_in[1];
    const int*   frame_label  = (const int*)d_in[2];
    const int*   frame_tlabel = (const int*)d_in[3];
    const int*   label  = (const int*)d_in[4];
    const float* norm_w = (const float*)d_in[5];
    const float* norm_b = (const float*)d_in[6];
    const float* head_w = (const float*)d_in[7];
    const float* head_b = (const float*)d_in[8];
    float* out = (float*)d_out;

    masked_sum_kernel<<<dim3(NSPLIT, BNUM), 256>>>(
        (const float4*)enc_out, (const float4*)pred_out,
        frame_label, frame_tlabel);

    tail_kernel<<<BNUM, 1024>>>(label, norm_w, norm_b, head_w, head_b, out);
}